// round 11
// baseline (speedup 1.0000x reference)
#include <cuda_runtime.h>
#include <cuda_pipeline_primitives.h>

#define B 256
#define S 512
#define T 128
#define STARTT 125
#define STOPT 126
#define TB_PITCH 132  // padded row pitch (floats) for smem transT

// 64MB part-history scratch: hist[b][s][t]
__device__ float g_hist[(size_t)B * S * T];

// ---------------------------------------------------------------------------
// Kernel 1: forward Viterbi max-plus recurrence. One block per batch.
// Thread j holds trans[:, j] in 128 scalar registers. ~85-90% of issue floor.
// (identical to the R9/R10 passing configuration)
// ---------------------------------------------------------------------------
__global__ __launch_bounds__(128, 2) void k_forward(
    const float* __restrict__ feats, const float* __restrict__ trans) {
    const int b = blockIdx.x;
    const int j = threadIdx.x;

    float c[T];
#pragma unroll
    for (int i = 0; i < T; i++) c[i] = trans[i * T + j];

    __shared__ __align__(16) float part[2][T];

    const float* fb = feats + (size_t)b * S * T;
    float* hb = g_hist + (size_t)b * S * T;

    float p0 = fb[j] + c[STARTT];
    part[0][j] = p0;
    hb[j] = p0;
    float e1 = fb[T + j];
    float e2 = fb[2 * T + j];
    __syncthreads();

#pragma unroll 1
    for (int s = 1; s < S; s++) {
        float ecur = e1;
        e1 = e2;
        int sf = s + 2 < S ? s + 2 : S - 1;  // clamp -> unconditional LDG
        e2 = fb[sf * T + j];

        const float4* pp = reinterpret_cast<const float4*>(part[(s - 1) & 1]);
        float4 v0 = pp[0];
        float m0 = v0.x + c[0];
        float m1 = v0.y + c[1];
        float m2 = v0.z + c[2];
        float m3 = v0.w + c[3];
#pragma unroll
        for (int q = 1; q < 32; q++) {
            float4 u = pp[q];
            m0 = fmaxf(m0, u.x + c[4 * q + 0]);
            m1 = fmaxf(m1, u.y + c[4 * q + 1]);
            m2 = fmaxf(m2, u.z + c[4 * q + 2]);
            m3 = fmaxf(m3, u.w + c[4 * q + 3]);
        }
        float np = fmaxf(fmaxf(m0, m1), fmaxf(m2, m3)) + ecur;
        part[s & 1][j] = np;
        hb[s * T + j] = np;
        __syncthreads();
    }
}

// monotonic float -> u32 key (order preserving for finite floats)
__device__ __forceinline__ unsigned fkey(float f) {
    unsigned u = __float_as_uint(f);
    return u ^ ((unsigned)((int)u >> 31) | 0x80000000u);
}

// first-index argmax over the warp's 4-per-lane keys; returns index to all
__device__ __forceinline__ int warp_argmax4(unsigned k0, unsigned k1,
                                            unsigned k2, unsigned k3, int l) {
    unsigned ka = (k0 > k1) ? k0 : k1;
    unsigned kb = (k2 > k3) ? k2 : k3;
    unsigned lm = (ka > kb) ? ka : kb;
    unsigned g = __reduce_max_sync(0xffffffffu, lm);
    unsigned bm = (k0 == g ? 1u : 0u) | (k1 == g ? 2u : 0u) |
                  (k2 == g ? 4u : 0u) | (k3 == g ? 8u : 0u);
    unsigned idxc = bm ? (unsigned)(4 * l + (__ffs((int)bm) - 1))
                       : 0x40000000u;
    return (int)__reduce_min_sync(0xffffffffu, idxc);
}

// ---------------------------------------------------------------------------
// Kernel 2: per-WARP DUAL-CHAIN traceback. Grid 32 x 128 threads; warp w of
// block g traces batches 8g+2w and 8g+2w+1, interleaved in the instruction
// stream -> while chain A waits on REDUX/LDS latency, chain B issues (ILP=2).
// Each chain has its own 4-slot cp.async smem ring; ONE commit per iteration
// (covering both chains' refills) keeps wait_prior(3) group accounting exact.
// ---------------------------------------------------------------------------
__global__ __launch_bounds__(128, 1) void k_traceback(
    const float* __restrict__ feats, const float* __restrict__ trans,
    const void* __restrict__ mask, float* __restrict__ out) {
    const int tid = threadIdx.x;
    const int wid = tid >> 5;
    const int l = tid & 31;
    const int base_b = blockIdx.x * 8 + wid * 2;  // chains base_b, base_b+1

    extern __shared__ float smem[];
    float* sT = smem;  // [T][TB_PITCH]
    float* ring[2];
    ring[0] = smem + T * TB_PITCH + (wid * 2 + 0) * 1024;  // 4 slots x 256
    ring[1] = smem + T * TB_PITCH + (wid * 2 + 1) * 1024;

    // cooperative transpose of trans into padded smem (one-time)
    for (int k = tid; k < T * T; k += 128) {
        int i = k >> 7;
        int jj = k & 127;
        sT[jj * TB_PITCH + i] = trans[k];
    }
    __syncthreads();

    const unsigned w0 = *(const unsigned*)mask;  // dtype signature

    int s0[2], ptrc[2];
    const float* hist_b[2];
    const float* feats_b[2];
    float* ob[2];

#pragma unroll
    for (int c = 0; c < 2; c++) {
        const int b = base_b + c;
        // ---- per-warp length: lane l counts 16 consecutive mask entries ----
        int cnt = 0;
        if (w0 == 0x01010101u) {  // 1-byte bool
            const uint4* m16 = (const uint4*)((const unsigned char*)mask +
                                              (size_t)b * S + l * 16);
            uint4 v = *m16;
            cnt = __popc(v.x) + __popc(v.y) + __popc(v.z) + __popc(v.w);
        } else if (w0 == 0x3F800000u) {  // float32
            const float* mf = (const float*)mask + (size_t)b * S + l * 16;
#pragma unroll
            for (int t = 0; t < 16; t++) cnt += (mf[t] != 0.f);
        } else if (w0 == 0x3F803F80u || w0 == 0x3C003C00u) {  // bf16 / f16
            const unsigned short* mh =
                (const unsigned short*)mask + (size_t)b * S + l * 16;
#pragma unroll
            for (int t = 0; t < 16; t++) cnt += (mh[t] != 0);
        } else {  // int32 0/1
            const int* mi = (const int*)mask + (size_t)b * S + l * 16;
#pragma unroll
            for (int t = 0; t < 16; t++) cnt += (mi[t] != 0);
        }
        cnt = __reduce_add_sync(0xffffffffu, cnt);
        const int last_pos = cnt - 1;

        hist_b[c] = g_hist + (size_t)b * S * T;
        feats_b[c] = feats + (size_t)b * S * T;

        // ---- final pointer: argmax_i(hist[last_pos][i] + trans[i][STOP]) --
        float4 h =
            reinterpret_cast<const float4*>(hist_b[c] + last_pos * T)[l];
        float4 tr = reinterpret_cast<const float4*>(sT + STOPT * TB_PITCH)[l];
        unsigned k0 = fkey(h.x + tr.x), k1 = fkey(h.y + tr.y);
        unsigned k2 = fkey(h.z + tr.z), k3 = fkey(h.w + tr.w);
        int pointer = warp_argmax4(k0, k1, k2, k3, l);

        ob[c] = out + (size_t)b * S;
        for (int s = last_pos + 1 + l; s < S - 1; s += 32) ob[c][s] = 0.0f;
        if (l == 0) {
            ob[c][S - 1] = (float)pointer;
            ob[c][last_pos] = (float)pointer;
        }
        ptrc[c] = pointer;
        s0[c] = last_pos - 1;
    }

    const int nsteps = (s0[0] > s0[1] ? s0[0] : s0[1]) + 1;
    if (nsteps <= 0) return;

    // ---- prologue: fill 4 ring slots for both chains ----
#pragma unroll
    for (int k = 0; k < 4; k++) {
#pragma unroll
        for (int c = 0; c < 2; c++) {
            int sp = s0[c] - k;
            if (sp < 0) sp = 0;
            __pipeline_memcpy_async(ring[c] + k * 256 + 4 * l,
                                    hist_b[c] + sp * T + 4 * l, 16);
            __pipeline_memcpy_async(ring[c] + k * 256 + 128 + 4 * l,
                                    feats_b[c] + (sp + 1) * T + 4 * l, 16);
        }
        __pipeline_commit();
    }

    for (int k = 0; k < nsteps; k++) {
        const int slot = k & 3;
        __pipeline_wait_prior(3);

        // consume rows for both chains
        const float* sb0 = ring[0] + slot * 256;
        const float* sb1 = ring[1] + slot * 256;
        float4 h0 = *reinterpret_cast<const float4*>(sb0 + 4 * l);
        float4 h1 = *reinterpret_cast<const float4*>(sb1 + 4 * l);
        float e0 = sb0[128 + ptrc[0]];
        float e1 = sb1[128 + ptrc[1]];

        // refill this slot for step k+4 (ptr-independent), ONE commit
#pragma unroll
        for (int c = 0; c < 2; c++) {
            int sp = s0[c] - k - 4;
            if (sp < 0) sp = 0;
            __pipeline_memcpy_async(ring[c] + slot * 256 + 4 * l,
                                    hist_b[c] + sp * T + 4 * l, 16);
            __pipeline_memcpy_async(ring[c] + slot * 256 + 128 + 4 * l,
                                    feats_b[c] + (sp + 1) * T + 4 * l, 16);
        }
        __pipeline_commit();

        // chain 0
        {
            float4 tc =
                reinterpret_cast<const float4*>(sT + ptrc[0] * TB_PITCH)[l];
            unsigned k0 = fkey((h0.x + tc.x) + e0);
            unsigned k1 = fkey((h0.y + tc.y) + e0);
            unsigned k2 = fkey((h0.z + tc.z) + e0);
            unsigned k3 = fkey((h0.w + tc.w) + e0);
            ptrc[0] = warp_argmax4(k0, k1, k2, k3, l);
            int sA = s0[0] - k;
            if (sA >= 0 && l == 0) ob[0][sA] = (float)ptrc[0];
        }
        // chain 1
        {
            float4 tc =
                reinterpret_cast<const float4*>(sT + ptrc[1] * TB_PITCH)[l];
            unsigned k0 = fkey((h1.x + tc.x) + e1);
            unsigned k1 = fkey((h1.y + tc.y) + e1);
            unsigned k2 = fkey((h1.z + tc.z) + e1);
            unsigned k3 = fkey((h1.w + tc.w) + e1);
            ptrc[1] = warp_argmax4(k0, k1, k2, k3, l);
            int sB = s0[1] - k;
            if (sB >= 0 && l == 0) ob[1][sB] = (float)ptrc[1];
        }
    }
}

// ---------------------------------------------------------------------------
extern "C" void kernel_launch(void* const* d_in, const int* in_sizes, int n_in,
                              void* d_out, int out_size) {
    // Identify inputs by element count:
    //   feats 16777216, transitions 16384, mask 131072
    const float* feats = nullptr;
    const void* mask = nullptr;
    const float* trans = nullptr;
    for (int i = 0; i < n_in; i++) {
        int n = in_sizes[i];
        if (n == B * S * T) feats = (const float*)d_in[i];
        else if (n == T * T) trans = (const float*)d_in[i];
        else mask = d_in[i];
    }
    float* out = (float*)d_out;
    (void)out_size;

    // smem: transT (67584 B) + 8 rings x 4096 B = 100352 B
    const int smem_tb = T * TB_PITCH * sizeof(float) + 8 * 1024 * 4;
    cudaFuncSetAttribute(k_traceback,
                         cudaFuncAttributeMaxDynamicSharedMemorySize, smem_tb);

    k_forward<<<B, T>>>(feats, trans);
    k_traceback<<<B / 8, T, smem_tb>>>(feats, trans, mask, out);
}

// round 12
// speedup vs baseline: 1.0423x; 1.0423x over previous
#include <cuda_runtime.h>
#include <cuda_pipeline_primitives.h>

#define B 256
#define S 512
#define T 128
#define STARTT 125
#define STOPT 126
#define TB_PITCH 132  // padded row pitch (floats) for smem transT

// 64MB part-history scratch: hist[b][s][t]
__device__ float g_hist[(size_t)B * S * T];

// ---------------------------------------------------------------------------
// Kernel 1: forward Viterbi max-plus recurrence. One block per batch.
// Thread j holds trans[:, j] in 128 scalar registers. ~88% of issue floor.
// (identical to the R9-R11 passing configuration)
// ---------------------------------------------------------------------------
__global__ __launch_bounds__(128, 2) void k_forward(
    const float* __restrict__ feats, const float* __restrict__ trans) {
    const int b = blockIdx.x;
    const int j = threadIdx.x;

    float c[T];
#pragma unroll
    for (int i = 0; i < T; i++) c[i] = trans[i * T + j];

    __shared__ __align__(16) float part[2][T];

    const float* fb = feats + (size_t)b * S * T;
    float* hb = g_hist + (size_t)b * S * T;

    float p0 = fb[j] + c[STARTT];
    part[0][j] = p0;
    hb[j] = p0;
    float e1 = fb[T + j];
    float e2 = fb[2 * T + j];
    __syncthreads();

#pragma unroll 1
    for (int s = 1; s < S; s++) {
        float ecur = e1;
        e1 = e2;
        int sf = s + 2 < S ? s + 2 : S - 1;  // clamp -> unconditional LDG
        e2 = fb[sf * T + j];

        const float4* pp = reinterpret_cast<const float4*>(part[(s - 1) & 1]);
        float4 v0 = pp[0];
        float m0 = v0.x + c[0];
        float m1 = v0.y + c[1];
        float m2 = v0.z + c[2];
        float m3 = v0.w + c[3];
#pragma unroll
        for (int q = 1; q < 32; q++) {
            float4 u = pp[q];
            m0 = fmaxf(m0, u.x + c[4 * q + 0]);
            m1 = fmaxf(m1, u.y + c[4 * q + 1]);
            m2 = fmaxf(m2, u.z + c[4 * q + 2]);
            m3 = fmaxf(m3, u.w + c[4 * q + 3]);
        }
        float np = fmaxf(fmaxf(m0, m1), fmaxf(m2, m3)) + ecur;
        part[s & 1][j] = np;
        hb[s * T + j] = np;
        __syncthreads();
    }
}

// monotonic float -> u32 key (order preserving for finite floats)
__device__ __forceinline__ unsigned fkey(float f) {
    unsigned u = __float_as_uint(f);
    return u ^ ((unsigned)((int)u >> 31) | 0x80000000u);
}

// first-index argmax over the warp's 4-per-lane keys; returns index to all.
// ONE warp-collective REDUX + 4 overlapping ballots (no second REDUX/shfl).
__device__ __forceinline__ int warp_argmax4(unsigned k0, unsigned k1,
                                            unsigned k2, unsigned k3, int l) {
    unsigned ka = (k0 > k1) ? k0 : k1;
    unsigned kb = (k2 > k3) ? k2 : k3;
    unsigned lm = (ka > kb) ? ka : kb;
    unsigned g = __reduce_max_sync(0xffffffffu, lm);
    unsigned b0 = __ballot_sync(0xffffffffu, k0 == g);
    unsigned b1 = __ballot_sync(0xffffffffu, k1 == g);
    unsigned b2 = __ballot_sync(0xffffffffu, k2 == g);
    unsigned b3 = __ballot_sync(0xffffffffu, k3 == g);
    unsigned all = b0 | b1 | b2 | b3;
    int l0 = __ffs((int)all) - 1;           // smallest lane with a hit
    unsigned bit = 1u << l0;
    int c = (b0 & bit) ? 0 : (b1 & bit) ? 1 : (b2 & bit) ? 2 : 3;
    return 4 * l0 + c;                      // lexicographic first index
}

// ---------------------------------------------------------------------------
// Kernel 2: per-WARP traceback (R9 structure: grid 64 x 4 warps, 1 chain per
// warp, refill between consume and argmax). hist/feats rows streamed through
// a 4-slot cp.async smem ring.
// ---------------------------------------------------------------------------
__global__ __launch_bounds__(128, 1) void k_traceback(
    const float* __restrict__ feats, const float* __restrict__ trans,
    const void* __restrict__ mask, float* __restrict__ out) {
    const int tid = threadIdx.x;
    const int wid = tid >> 5;
    const int l = tid & 31;
    const int b = blockIdx.x * 4 + wid;

    extern __shared__ float smem[];
    float* sT = smem;                                  // [T][TB_PITCH]
    float* wring = smem + T * TB_PITCH + wid * 1024;   // 4 slots x 256 floats

    // cooperative transpose of trans into padded smem (one-time)
    for (int k = tid; k < T * T; k += 128) {
        int i = k >> 7;
        int jj = k & 127;
        sT[jj * TB_PITCH + i] = trans[k];
    }
    __syncthreads();

    // ---- per-warp length: lane l counts 16 consecutive mask entries ----
    const unsigned w0 = *(const unsigned*)mask;  // dtype signature
    int cnt = 0;
    if (w0 == 0x01010101u) {  // 1-byte bool
        const uint4* m16 = (const uint4*)((const unsigned char*)mask +
                                          (size_t)b * S + l * 16);
        uint4 v = *m16;
        cnt = __popc(v.x) + __popc(v.y) + __popc(v.z) + __popc(v.w);
    } else if (w0 == 0x3F800000u) {  // float32
        const float* mf = (const float*)mask + (size_t)b * S + l * 16;
#pragma unroll
        for (int t = 0; t < 16; t++) cnt += (mf[t] != 0.f);
    } else if (w0 == 0x3F803F80u || w0 == 0x3C003C00u) {  // bf16 / f16
        const unsigned short* mh =
            (const unsigned short*)mask + (size_t)b * S + l * 16;
#pragma unroll
        for (int t = 0; t < 16; t++) cnt += (mh[t] != 0);
    } else {  // int32 0/1
        const int* mi = (const int*)mask + (size_t)b * S + l * 16;
#pragma unroll
        for (int t = 0; t < 16; t++) cnt += (mi[t] != 0);
    }
    cnt = __reduce_add_sync(0xffffffffu, cnt);
    const int last_pos = cnt - 1;

    const float* hist_b = g_hist + (size_t)b * S * T;
    const float* feats_b = feats + (size_t)b * S * T;

    // ---- final pointer: argmax_i(hist[last_pos][i] + trans[i][STOP]) ----
    int pointer;
    {
        float4 h = reinterpret_cast<const float4*>(hist_b + last_pos * T)[l];
        float4 tr = reinterpret_cast<const float4*>(sT + STOPT * TB_PITCH)[l];
        unsigned k0 = fkey(h.x + tr.x), k1 = fkey(h.y + tr.y);
        unsigned k2 = fkey(h.z + tr.z), k3 = fkey(h.w + tr.w);
        pointer = warp_argmax4(k0, k1, k2, k3, l);
    }

    float* ob = out + (size_t)b * S;

    // positions past the sequence: zeros (matches zeroed back_points rows)
    for (int s = last_pos + 1 + l; s < S - 1; s += 32) ob[s] = 0.0f;
    if (l == 0) {
        ob[S - 1] = (float)pointer;
        ob[last_pos] = (float)pointer;
    }

    int ptr = pointer;
    const int s0 = last_pos - 1;
    if (s0 < 0) return;

    // ---- prologue: fill 4 ring slots (steps s0 .. s0-3) ----
#pragma unroll
    for (int k = 0; k < 4; k++) {
        int sp = s0 - k;
        if (sp < 0) sp = 0;
        __pipeline_memcpy_async(wring + k * 256 + 4 * l,
                                hist_b + sp * T + 4 * l, 16);
        __pipeline_memcpy_async(wring + k * 256 + 128 + 4 * l,
                                feats_b + (sp + 1) * T + 4 * l, 16);
        __pipeline_commit();
    }

    int slot = 0;
    for (int s = s0; s >= 0; --s) {
        // wait only for the oldest outstanding group (this slot's data)
        __pipeline_wait_prior(3);
        const float* sb = wring + slot * 256;
        float4 h = *reinterpret_cast<const float4*>(sb + 4 * l);
        // scalar e = feats[b][s+1][ptr]: uniform-address broadcast LDS
        float e = sb[128 + ptr];

        // refill this slot for step s-4 (ptr-independent addresses)
        int sp = s - 4;
        if (sp < 0) sp = 0;
        __pipeline_memcpy_async(wring + slot * 256 + 4 * l,
                                hist_b + sp * T + 4 * l, 16);
        __pipeline_memcpy_async(wring + slot * 256 + 128 + 4 * l,
                                feats_b + (sp + 1) * T + 4 * l, 16);
        __pipeline_commit();

        // trans[:, ptr] chunk from padded smem (LDS.128, conflict-free)
        float4 tc = reinterpret_cast<const float4*>(sT + ptr * TB_PITCH)[l];

        // exact replication of reference: (part + trans) + e, argmax first-idx
        unsigned k0 = fkey((h.x + tc.x) + e);
        unsigned k1 = fkey((h.y + tc.y) + e);
        unsigned k2 = fkey((h.z + tc.z) + e);
        unsigned k3 = fkey((h.w + tc.w) + e);
        ptr = warp_argmax4(k0, k1, k2, k3, l);
        if (l == 0) ob[s] = (float)ptr;

        slot = (slot + 1) & 3;
    }
}

// ---------------------------------------------------------------------------
extern "C" void kernel_launch(void* const* d_in, const int* in_sizes, int n_in,
                              void* d_out, int out_size) {
    // Identify inputs by element count:
    //   feats 16777216, transitions 16384, mask 131072
    const float* feats = nullptr;
    const void* mask = nullptr;
    const float* trans = nullptr;
    for (int i = 0; i < n_in; i++) {
        int n = in_sizes[i];
        if (n == B * S * T) feats = (const float*)d_in[i];
        else if (n == T * T) trans = (const float*)d_in[i];
        else mask = d_in[i];
    }
    float* out = (float*)d_out;
    (void)out_size;

    // smem: transT (67584 B) + 4 warps x 4 slots x 256 floats (16384 B)
    const int smem_tb = T * TB_PITCH * sizeof(float) + 4 * 4 * 256 * 4;
    cudaFuncSetAttribute(k_traceback,
                         cudaFuncAttributeMaxDynamicSharedMemorySize, smem_tb);

    k_forward<<<B, T>>>(feats, trans);
    k_traceback<<<B / 4, T, smem_tb>>>(feats, trans, mask, out);
}